// round 6
// baseline (speedup 1.0000x reference)
#include <cuda_runtime.h>

#define T_STEPS 8192
#define MDIM    1024
#define INDIM   1024
#define XCOLS   5120
#define NCTA    128
#define NTHR    256
#define CELLS   8      // memory cells owned per CTA (1024/128)

// ---------------- scratch (static device globals; no allocation) -------------
__device__ float    g_xproj[(size_t)T_STEPS * XCOLS];   // 160 MB
__device__ float    g_h[MDIM];                           // h broadcast buffer
__device__ float    g_a[MDIM];                           // a = z*tanh(c) buffer
__device__ unsigned g_ctr[2 * T_STEPS];                  // barrier counters (epoch-based, replay safe)

// ---- XLA-matched transcendentals ---------------------------------------------
// tanh: XLA (CPU & GPU) lowers f32 tanh to the Eigen-derived rational
//   approximation (EmitFastTanh): |x|<4e-4 -> x; clamp; x*P(x2)/Q(x2), FMA form.
// sigmoid: XLA's logistic expander uses the exp form 1/(1+exp(-x)).
__device__ __forceinline__ float xla_tanh(float x) {
    float xc = fminf(fmaxf(x, -9.0f), 9.0f);
    float x2 = xc * xc;
    float p = fmaf(x2, -2.76076847742355e-16f, 2.00018790482477e-13f);
    p = fmaf(x2, p, -8.60467152213735e-11f);
    p = fmaf(x2, p,  5.12229709037114e-08f);
    p = fmaf(x2, p,  1.48572235717979e-05f);
    p = fmaf(x2, p,  6.37261928875436e-04f);
    p = fmaf(x2, p,  4.89352455891786e-03f);
    float num = __fmul_rn(xc, p);
    float q = fmaf(x2, 1.19825839466702e-06f, 1.18534705686654e-04f);
    q = fmaf(x2, q, 2.26843463243900e-03f);
    q = fmaf(x2, q, 4.89352518554385e-03f);
    return (fabsf(x) < 4.0e-4f) ? x : __fdiv_rn(num, q);
}
__device__ __forceinline__ float xla_sigmoid(float x) {
    // 1 / (1 + exp(-x)); exp via ex2 (err ~2^-21), IEEE divide
    float e;
    asm("ex2.approx.f32 %0, %1;" : "=f"(e) : "f"(-x * 1.4426950408889634f));
    return __fdiv_rn(1.0f, __fadd_rn(1.0f, e));
}

// Grid barrier, replay-safe: counters only ever increase; each run each CTA
// arrives exactly once per slot, so target epoch = my/NCTA + 1.
__device__ __forceinline__ void gbar(int slot) {
    __syncthreads();
    if (threadIdx.x == 0) {
        __threadfence();                       // release prior stores
        unsigned* c  = &g_ctr[slot];
        unsigned my  = atomicAdd(c, 1u);
        unsigned tgt = (my / NCTA + 1u) * (unsigned)NCTA;
        while (*((volatile unsigned*)c) < tgt) { }
        __threadfence();                       // acquire
    }
    __syncthreads();
}

// ---------------- Kernel 1: xproj = inputs @ Wx^T + bx  (NT SGEMM, fp32) -----
// C[8192,5120] = A[8192,1024] * B[5120,1024]^T ; 128x128 tile, BK=8, 8x8/thr
__global__ void __launch_bounds__(256) xproj_gemm(
    const float* __restrict__ A,
    const float* __restrict__ B,
    const float* __restrict__ bias)
{
    __shared__ float As[8][128];
    __shared__ float Bs[8][128];

    int tid = threadIdx.x;
    int tx  = tid & 15, ty = tid >> 4;
    int m0  = blockIdx.y * 128, n0 = blockIdx.x * 128;
    int lrow = tid >> 1, lk = (tid & 1) * 4;

    const float* Ap = A + (size_t)(m0 + lrow) * INDIM + lk;
    const float* Bp = B + (size_t)(n0 + lrow) * INDIM + lk;

    float acc[8][8];
#pragma unroll
    for (int i = 0; i < 8; i++)
#pragma unroll
        for (int j = 0; j < 8; j++) acc[i][j] = 0.0f;

    for (int k0 = 0; k0 < INDIM; k0 += 8) {
        float4 av = *(const float4*)(Ap + k0);
        float4 bv = *(const float4*)(Bp + k0);
        As[lk + 0][lrow] = av.x; As[lk + 1][lrow] = av.y;
        As[lk + 2][lrow] = av.z; As[lk + 3][lrow] = av.w;
        Bs[lk + 0][lrow] = bv.x; Bs[lk + 1][lrow] = bv.y;
        Bs[lk + 2][lrow] = bv.z; Bs[lk + 3][lrow] = bv.w;
        __syncthreads();
#pragma unroll
        for (int kk = 0; kk < 8; kk++) {
            float a[8], b[8];
            *(float4*)&a[0] = *(const float4*)&As[kk][ty * 8];
            *(float4*)&a[4] = *(const float4*)&As[kk][ty * 8 + 4];
            *(float4*)&b[0] = *(const float4*)&Bs[kk][tx * 8];
            *(float4*)&b[4] = *(const float4*)&Bs[kk][tx * 8 + 4];
#pragma unroll
            for (int i = 0; i < 8; i++)
#pragma unroll
                for (int j = 0; j < 8; j++) acc[i][j] += a[i] * b[j];
        }
        __syncthreads();
    }

    float bb[8];
#pragma unroll
    for (int j = 0; j < 8; j++) bb[j] = bias[n0 + tx * 8 + j];
#pragma unroll
    for (int i = 0; i < 8; i++) {
        float* crow = g_xproj + (size_t)(m0 + ty * 8 + i) * XCOLS + n0 + tx * 8;
        float4 v0 = make_float4(__fadd_rn(acc[i][0], bb[0]), __fadd_rn(acc[i][1], bb[1]),
                                __fadd_rn(acc[i][2], bb[2]), __fadd_rn(acc[i][3], bb[3]));
        float4 v1 = make_float4(__fadd_rn(acc[i][4], bb[4]), __fadd_rn(acc[i][5], bb[5]),
                                __fadd_rn(acc[i][6], bb[6]), __fadd_rn(acc[i][7], bb[7]));
        *(float4*)crow       = v0;
        *(float4*)(crow + 4) = v1;
    }
}

// ---------------- Kernel 2: persistent recurrent scan ------------------------
// 128 CTAs x 256 threads. CTA owns cells [8*cta, 8*cta+8).
// Warp w (0..7) owns slice rows 4w..4w+3 of the 32-row Wh slice (row s = gate*8 + cell),
// and Wm row = cell w. Lane l owns cols {128*c4 + 4l + k : c4<8, k<4} (32 cols, float4).
__global__ void __launch_bounds__(NTHR, 1) ulstm_scan(
    const float* __restrict__ Wh, const float* __restrict__ bh,
    const float* __restrict__ Wm, const float* __restrict__ bm,
    float* __restrict__ out)
{
    __shared__ float4 h4_s[MDIM / 4];
    __shared__ float4 a4_s[MDIM / 4];
    __shared__ float  hp_s[32];
    __shared__ float  gi_s[CELLS], go_s[CELLS], gf_s[CELLS], gu_s[CELLS];
    __shared__ float  c_s[CELLS];
    __shared__ float  bh_s[32];
    __shared__ float  bm_s[CELLS];

    const int tid = threadIdx.x;
    const int w   = tid >> 5;
    const int l   = tid & 31;
    const int cta = blockIdx.x;

    // ---- load weights into registers (persist across all 8192 steps) ----
    float4 wa[4][8];
#pragma unroll
    for (int r = 0; r < 4; r++) {
        int s   = 4 * w + r;
        int row = (s >> 3) * MDIM + cta * CELLS + (s & 7);
        const float4* src = (const float4*)(Wh + (size_t)row * MDIM);
#pragma unroll
        for (int c4 = 0; c4 < 8; c4++) wa[r][c4] = src[c4 * 32 + l];
    }
    float4 wmr[8];
    {
        int row = cta * CELLS + w;
        const float4* src = (const float4*)(Wm + (size_t)row * MDIM);
#pragma unroll
        for (int c4 = 0; c4 < 8; c4++) wmr[c4] = src[c4 * 32 + l];
    }
    if (tid < 32) bh_s[tid] = bh[(tid >> 3) * MDIM + cta * CELLS + (tid & 7)];
    if (tid < CELLS) { bm_s[tid] = bm[cta * CELLS + tid]; c_s[tid] = 0.0f; }
    __syncthreads();

    const float4* gh4 = (const float4*)g_h;
    const float4* ga4 = (const float4*)g_a;

    for (int t = 0; t < T_STEPS; t++) {
        // prefetch this step's xproj gate inputs early (DRAM latency hidden by matvec)
        float ix = 0.f, ox = 0.f, zx = 0.f, fx = 0.f, uxv = 0.f;
        if (tid < CELLS) {
            const float* xr = g_xproj + (size_t)t * XCOLS + cta * CELLS + tid;
            ix  = xr[0];
            ox  = xr[MDIM];
            zx  = xr[2 * MDIM];
            fx  = xr[3 * MDIM];
            uxv = xr[4 * MDIM];
        }

        // ---------- Phase A: hp = Wh @ h + bh ----------
        if (t > 0) {
            h4_s[tid] = gh4[tid];
            __syncthreads();
            float acc0 = 0.f, acc1 = 0.f, acc2 = 0.f, acc3 = 0.f;
#pragma unroll
            for (int c4 = 0; c4 < 8; c4++) {
                float4 hv = h4_s[c4 * 32 + l];
                acc0 += wa[0][c4].x * hv.x + wa[0][c4].y * hv.y + wa[0][c4].z * hv.z + wa[0][c4].w * hv.w;
                acc1 += wa[1][c4].x * hv.x + wa[1][c4].y * hv.y + wa[1][c4].z * hv.z + wa[1][c4].w * hv.w;
                acc2 += wa[2][c4].x * hv.x + wa[2][c4].y * hv.y + wa[2][c4].z * hv.z + wa[2][c4].w * hv.w;
                acc3 += wa[3][c4].x * hv.x + wa[3][c4].y * hv.y + wa[3][c4].z * hv.z + wa[3][c4].w * hv.w;
            }
#pragma unroll
            for (int off = 16; off > 0; off >>= 1) {
                acc0 += __shfl_xor_sync(0xffffffffu, acc0, off);
                acc1 += __shfl_xor_sync(0xffffffffu, acc1, off);
                acc2 += __shfl_xor_sync(0xffffffffu, acc2, off);
                acc3 += __shfl_xor_sync(0xffffffffu, acc3, off);
            }
            if (l == 0) {
                hp_s[4 * w + 0] = __fadd_rn(acc0, bh_s[4 * w + 0]);
                hp_s[4 * w + 1] = __fadd_rn(acc1, bh_s[4 * w + 1]);
                hp_s[4 * w + 2] = __fadd_rn(acc2, bh_s[4 * w + 2]);
                hp_s[4 * w + 3] = __fadd_rn(acc3, bh_s[4 * w + 3]);
            }
        } else {
            if (tid < 32) hp_s[tid] = bh_s[tid];   // h0 = 0 -> hp = bh
        }
        __syncthreads();

        // ---------- gates + a = z * tanh(c)  (XLA-matched elementwise) -------
        if (tid < CELLS) {
            float i_ = xla_sigmoid(__fadd_rn(ix, hp_s[tid]));
            float o_ = xla_sigmoid(__fadd_rn(ox, hp_s[8 + tid]));
            float z_ = xla_sigmoid(__fadd_rn(zx, hp_s[16 + tid]));
            float f_ = xla_sigmoid(__fadd_rn(fx, hp_s[24 + tid]));
            float a_ = __fmul_rn(z_, xla_tanh(c_s[tid]));
            gi_s[tid] = i_; go_s[tid] = o_; gf_s[tid] = f_; gu_s[tid] = uxv;
            g_a[cta * CELLS + tid] = a_;
            __threadfence();
        }
        gbar(2 * t);

        // ---------- Phase B: u = tanh(ux + Wm@a + bm); state update ----------
        a4_s[tid] = ga4[tid];
        __syncthreads();
        float acc = 0.f;
#pragma unroll
        for (int c4 = 0; c4 < 8; c4++) {
            float4 av = a4_s[c4 * 32 + l];
            acc += wmr[c4].x * av.x + wmr[c4].y * av.y + wmr[c4].z * av.z + wmr[c4].w * av.w;
        }
#pragma unroll
        for (int off = 16; off > 0; off >>= 1)
            acc += __shfl_xor_sync(0xffffffffu, acc, off);

        if (l == 0) {
            // u = tanh((ux + dot) + bm)  -- same association as reference
            float u  = xla_tanh(__fadd_rn(__fadd_rn(gu_s[w], acc), bm_s[w]));
            // c2 = i*u + f*c  as separate mul/mul/add (match HLO, no FMA contraction)
            float c2 = __fadd_rn(__fmul_rn(gi_s[w], u), __fmul_rn(gf_s[w], c_s[w]));
            float h2 = __fmul_rn(go_s[w], xla_tanh(c2));
            c_s[w] = c2;
            if (t == T_STEPS - 1) {
                out[cta * CELLS + w]        = c2;
                out[MDIM + cta * CELLS + w] = h2;
            } else {
                g_h[cta * CELLS + w] = h2;
                __threadfence();
            }
        }
        if (t < T_STEPS - 1) gbar(2 * t + 1);
    }
}

// ---------------- launch ------------------------------------------------------
extern "C" void kernel_launch(void* const* d_in, const int* in_sizes, int n_in,
                              void* d_out, int out_size)
{
    const float* inputs = (const float*)d_in[0];
    const float* Wx     = (const float*)d_in[1];
    const float* bx     = (const float*)d_in[2];
    const float* Wh     = (const float*)d_in[3];
    const float* bh     = (const float*)d_in[4];
    const float* Wm     = (const float*)d_in[5];
    const float* bm     = (const float*)d_in[6];
    float* out = (float*)d_out;

    dim3 ggrid(XCOLS / 128, T_STEPS / 128);   // (40, 64)
    xproj_gemm<<<ggrid, 256>>>(inputs, Wx, bx);

    ulstm_scan<<<NCTA, NTHR>>>(Wh, bh, Wm, bm, out);
}

// round 7
// speedup vs baseline: 1.2310x; 1.2310x over previous
#include <cuda_runtime.h>

#define T_STEPS 8192
#define MDIM    1024
#define INDIM   1024
#define XCOLS   5120
#define NCTA    128
#define NTHR    256
#define CELLS   8      // memory cells owned per CTA (1024/128)

// ---------------- scratch (static device globals; no allocation) -------------
__device__ float    g_xproj[(size_t)T_STEPS * XCOLS];   // 160 MB
__device__ float    g_h[MDIM];                           // h broadcast buffer
__device__ float    g_a[MDIM];                           // a = z*tanh(c) buffer
__device__ unsigned g_ctr[2 * T_STEPS];                  // barrier counters (monotonic)
__device__ unsigned g_epoch;                             // completed scan launches

// ---- XLA-matched transcendentals ---------------------------------------------
// tanh: Eigen-derived rational (XLA EmitFastTanh); sigmoid: 1/(1+exp(-x)).
__device__ __forceinline__ float xla_tanh(float x) {
    float xc = fminf(fmaxf(x, -9.0f), 9.0f);
    float x2 = xc * xc;
    float p = fmaf(x2, -2.76076847742355e-16f, 2.00018790482477e-13f);
    p = fmaf(x2, p, -8.60467152213735e-11f);
    p = fmaf(x2, p,  5.12229709037114e-08f);
    p = fmaf(x2, p,  1.48572235717979e-05f);
    p = fmaf(x2, p,  6.37261928875436e-04f);
    p = fmaf(x2, p,  4.89352455891786e-03f);
    float num = __fmul_rn(xc, p);
    float q = fmaf(x2, 1.19825839466702e-06f, 1.18534705686654e-04f);
    q = fmaf(x2, q, 2.26843463243900e-03f);
    q = fmaf(x2, q, 4.89352518554385e-03f);
    return (fabsf(x) < 4.0e-4f) ? x : __fdiv_rn(num, q);
}
__device__ __forceinline__ float xla_sigmoid(float x) {
    float e;
    asm("ex2.approx.f32 %0, %1;" : "=f"(e) : "f"(-x * 1.4426950408889634f));
    return __fdiv_rn(1.0f, __fadd_rn(1.0f, e));
}

// Fence-free grid barrier. Target known in advance via launch epoch:
// every used slot receives exactly NCTA increments per launch, so at launch
// start every slot holds epoch*NCTA. Arrival = fire-and-forget release red;
// wait = acquire-load spin. No MEMBAR.GPU, no CCTL.IVALL, no ATOMG return.
__device__ __forceinline__ void gbar(int slot, unsigned target) {
    __syncthreads();
    if (threadIdx.x == 0) {
        unsigned* c = &g_ctr[slot];
        asm volatile("red.release.gpu.global.add.u32 [%0], 1;" :: "l"(c) : "memory");
        unsigned v;
        do {
            asm volatile("ld.acquire.gpu.global.u32 %0, [%1];" : "=r"(v) : "l"(c) : "memory");
        } while (v < target);
    }
    __syncthreads();
}

// ---------------- Kernel 1: xproj = inputs @ Wx^T + bx  (NT SGEMM, fp32) -----
__global__ void __launch_bounds__(256) xproj_gemm(
    const float* __restrict__ A,
    const float* __restrict__ B,
    const float* __restrict__ bias)
{
    __shared__ float As[8][128];
    __shared__ float Bs[8][128];

    int tid = threadIdx.x;
    int tx  = tid & 15, ty = tid >> 4;
    int m0  = blockIdx.y * 128, n0 = blockIdx.x * 128;
    int lrow = tid >> 1, lk = (tid & 1) * 4;

    const float* Ap = A + (size_t)(m0 + lrow) * INDIM + lk;
    const float* Bp = B + (size_t)(n0 + lrow) * INDIM + lk;

    float acc[8][8];
#pragma unroll
    for (int i = 0; i < 8; i++)
#pragma unroll
        for (int j = 0; j < 8; j++) acc[i][j] = 0.0f;

    for (int k0 = 0; k0 < INDIM; k0 += 8) {
        float4 av = *(const float4*)(Ap + k0);
        float4 bv = *(const float4*)(Bp + k0);
        As[lk + 0][lrow] = av.x; As[lk + 1][lrow] = av.y;
        As[lk + 2][lrow] = av.z; As[lk + 3][lrow] = av.w;
        Bs[lk + 0][lrow] = bv.x; Bs[lk + 1][lrow] = bv.y;
        Bs[lk + 2][lrow] = bv.z; Bs[lk + 3][lrow] = bv.w;
        __syncthreads();
#pragma unroll
        for (int kk = 0; kk < 8; kk++) {
            float a[8], b[8];
            *(float4*)&a[0] = *(const float4*)&As[kk][ty * 8];
            *(float4*)&a[4] = *(const float4*)&As[kk][ty * 8 + 4];
            *(float4*)&b[0] = *(const float4*)&Bs[kk][tx * 8];
            *(float4*)&b[4] = *(const float4*)&Bs[kk][tx * 8 + 4];
#pragma unroll
            for (int i = 0; i < 8; i++)
#pragma unroll
                for (int j = 0; j < 8; j++) acc[i][j] += a[i] * b[j];
        }
        __syncthreads();
    }

    float bb[8];
#pragma unroll
    for (int j = 0; j < 8; j++) bb[j] = bias[n0 + tx * 8 + j];
#pragma unroll
    for (int i = 0; i < 8; i++) {
        float* crow = g_xproj + (size_t)(m0 + ty * 8 + i) * XCOLS + n0 + tx * 8;
        float4 v0 = make_float4(__fadd_rn(acc[i][0], bb[0]), __fadd_rn(acc[i][1], bb[1]),
                                __fadd_rn(acc[i][2], bb[2]), __fadd_rn(acc[i][3], bb[3]));
        float4 v1 = make_float4(__fadd_rn(acc[i][4], bb[4]), __fadd_rn(acc[i][5], bb[5]),
                                __fadd_rn(acc[i][6], bb[6]), __fadd_rn(acc[i][7], bb[7]));
        *(float4*)crow       = v0;
        *(float4*)(crow + 4) = v1;
    }
}

// ---------------- Kernel 2: persistent recurrent scan ------------------------
__global__ void __launch_bounds__(NTHR, 1) ulstm_scan(
    const float* __restrict__ Wh, const float* __restrict__ bh,
    const float* __restrict__ Wm, const float* __restrict__ bm,
    float* __restrict__ out)
{
    __shared__ float4 h4_s[MDIM / 4];
    __shared__ float4 a4_s[MDIM / 4];
    __shared__ float  hp_s[32];
    __shared__ float  gate_s[32];   // [gate*8+cell]: i(0..7) o(8..15) z(16..23) f(24..31)
    __shared__ float  gu_s[CELLS];
    __shared__ float  tc_s[CELLS];  // tanh(c) carried from previous step
    __shared__ float  c_s[CELLS];
    __shared__ float  bh_s[32];
    __shared__ float  bm_s[CELLS];

    const int tid = threadIdx.x;
    const int w   = tid >> 5;
    const int l   = tid & 31;
    const int cta = blockIdx.x;

    const unsigned target = (*((volatile unsigned*)&g_epoch) + 1u) * (unsigned)NCTA;

    // ---- load weights into registers (persist across all 8192 steps) ----
    float4 wa[4][8];
#pragma unroll
    for (int r = 0; r < 4; r++) {
        int s   = 4 * w + r;
        int row = (s >> 3) * MDIM + cta * CELLS + (s & 7);
        const float4* src = (const float4*)(Wh + (size_t)row * MDIM);
#pragma unroll
        for (int c4 = 0; c4 < 8; c4++) wa[r][c4] = src[c4 * 32 + l];
    }
    float4 wmr[8];
    {
        int row = cta * CELLS + w;
        const float4* src = (const float4*)(Wm + (size_t)row * MDIM);
#pragma unroll
        for (int c4 = 0; c4 < 8; c4++) wmr[c4] = src[c4 * 32 + l];
    }
    if (tid < 32) bh_s[tid] = bh[(tid >> 3) * MDIM + cta * CELLS + (tid & 7)];
    if (tid < CELLS) { bm_s[tid] = bm[cta * CELLS + tid]; c_s[tid] = 0.0f; tc_s[tid] = 0.0f; }
    __syncthreads();

    const float4* gh4 = (const float4*)g_h;
    const float4* ga4 = (const float4*)g_a;

    for (int t = 0; t < T_STEPS; t++) {
        // prefetch this step's xproj gate inputs (consumed after phase A)
        float xg = 0.f, uxr = 0.f;
        if (tid < 32) {
            const float* xr = g_xproj + (size_t)t * XCOLS + (tid >> 3) * MDIM + cta * CELLS + (tid & 7);
            xg = xr[0];
            if (tid < 8) uxr = xr[4 * MDIM];
        }

        // ---------- Phase A: hp = Wh @ h + bh ----------
        if (t > 0) {
            h4_s[tid] = __ldcg(gh4 + tid);
            __syncthreads();
            float acc0 = 0.f, acc1 = 0.f, acc2 = 0.f, acc3 = 0.f;
#pragma unroll
            for (int c4 = 0; c4 < 8; c4++) {
                float4 hv = h4_s[c4 * 32 + l];
                acc0 += wa[0][c4].x * hv.x + wa[0][c4].y * hv.y + wa[0][c4].z * hv.z + wa[0][c4].w * hv.w;
                acc1 += wa[1][c4].x * hv.x + wa[1][c4].y * hv.y + wa[1][c4].z * hv.z + wa[1][c4].w * hv.w;
                acc2 += wa[2][c4].x * hv.x + wa[2][c4].y * hv.y + wa[2][c4].z * hv.z + wa[2][c4].w * hv.w;
                acc3 += wa[3][c4].x * hv.x + wa[3][c4].y * hv.y + wa[3][c4].z * hv.z + wa[3][c4].w * hv.w;
            }
#pragma unroll
            for (int off = 16; off > 0; off >>= 1) {
                acc0 += __shfl_xor_sync(0xffffffffu, acc0, off);
                acc1 += __shfl_xor_sync(0xffffffffu, acc1, off);
                acc2 += __shfl_xor_sync(0xffffffffu, acc2, off);
                acc3 += __shfl_xor_sync(0xffffffffu, acc3, off);
            }
            if (l == 0) {
                hp_s[4 * w + 0] = __fadd_rn(acc0, bh_s[4 * w + 0]);
                hp_s[4 * w + 1] = __fadd_rn(acc1, bh_s[4 * w + 1]);
                hp_s[4 * w + 2] = __fadd_rn(acc2, bh_s[4 * w + 2]);
                hp_s[4 * w + 3] = __fadd_rn(acc3, bh_s[4 * w + 3]);
            }
        } else {
            if (tid < 32) hp_s[tid] = bh_s[tid];   // h0 = 0 -> hp = bh
        }
        __syncthreads();

        // ---------- gates (parallel across warp 0) + a = z * tanh(c) ---------
        if (tid < 32) {
            if (tid < 8) gu_s[tid] = uxr;
            float s = xla_sigmoid(__fadd_rn(xg, hp_s[tid]));
            gate_s[tid] = s;
            __syncwarp();
            if (tid < 8)
                g_a[cta * CELLS + tid] = __fmul_rn(gate_s[16 + tid], tc_s[tid]);
        }
        gbar(2 * t, target);

        // ---------- Phase B: u = tanh(ux + Wm@a + bm); state update ----------
        a4_s[tid] = __ldcg(ga4 + tid);
        __syncthreads();
        float acc = 0.f;
#pragma unroll
        for (int c4 = 0; c4 < 8; c4++) {
            float4 av = a4_s[c4 * 32 + l];
            acc += wmr[c4].x * av.x + wmr[c4].y * av.y + wmr[c4].z * av.z + wmr[c4].w * av.w;
        }
#pragma unroll
        for (int off = 16; off > 0; off >>= 1)
            acc += __shfl_xor_sync(0xffffffffu, acc, off);

        if (l == 0) {
            float u  = xla_tanh(__fadd_rn(__fadd_rn(gu_s[w], acc), bm_s[w]));
            float c2 = __fadd_rn(__fmul_rn(gate_s[w], u), __fmul_rn(gate_s[24 + w], c_s[w]));
            float th = xla_tanh(c2);
            float h2 = __fmul_rn(gate_s[8 + w], th);
            c_s[w]  = c2;
            tc_s[w] = th;    // reused next step: a = z * tanh(c)
            if (t == T_STEPS - 1) {
                out[cta * CELLS + w]        = c2;
                out[MDIM + cta * CELLS + w] = h2;
            } else {
                g_h[cta * CELLS + w] = h2;
            }
        }
        if (t < T_STEPS - 1) gbar(2 * t + 1, target);
    }

    // one epoch bump per launch (after the final full barrier)
    if (cta == 0 && tid == 0)
        asm volatile("red.global.add.u32 [%0], 1;" :: "l"(&g_epoch) : "memory");
}

// ---------------- launch ------------------------------------------------------
extern "C" void kernel_launch(void* const* d_in, const int* in_sizes, int n_in,
                              void* d_out, int out_size)
{
    const float* inputs = (const float*)d_in[0];
    const float* Wx     = (const float*)d_in[1];
    const float* bx     = (const float*)d_in[2];
    const float* Wh     = (const float*)d_in[3];
    const float* bh     = (const float*)d_in[4];
    const float* Wm     = (const float*)d_in[5];
    const float* bm     = (const float*)d_in[6];
    float* out = (float*)d_out;

    dim3 ggrid(XCOLS / 128, T_STEPS / 128);   // (40, 64)
    xproj_gemm<<<ggrid, 256>>>(inputs, Wx, bx);

    ulstm_scan<<<NCTA, NTHR>>>(Wh, bh, Wm, bm, out);
}